// round 16
// baseline (speedup 1.0000x reference)
#include <cuda_runtime.h>
#include <cuda_fp16.h>
#include <math.h>
#include <stdint.h>

// Problem constants
#define B_SZ   4096
#define N_AG   11
#define BN_ROWS (B_SZ * N_AG)      // 45056
#define MTILES  (BN_ROWS / 128)    // 352

// ---------------- device scratch ----------------
__device__ float g_Weff[48 * 256];
__device__ float g_ceffp[12 * 256];
__device__ float g_G[48 * 256];
__device__ float g_cb[11 * 256];
__device__ float g_zero64[64];     // zero bias (never written)

// fp16 activations
__device__ __half g_ft [(size_t)BN_ROWS * 256];
__device__ __half g_agg[(size_t)BN_ROWS * 256];
__device__ __half g_hag[(size_t)BN_ROWS * 256];
__device__ __half g_int[(size_t)BN_ROWS * 256];
__device__ __half g_hyp[(size_t)BN_ROWS * 256];
__device__ __half g_fea[(size_t)BN_ROWS * 64];
// fp16 transposed weights [n][K]
__device__ __half g_Wmsg_t[256 * 512];
__device__ __half g_Whyp_t[256 * 512];
__device__ __half g_Wout_t[128 * 1536];
__device__ __half g_Wlin_t[64 * 256];
__device__ __half g_Wqz_t [64 * 128];

// ---------------- helpers ----------------
#define SWZ(o) ((o) ^ (((o) >> 3) & 0x70))
__device__ __forceinline__ uint32_t smem_u32(const void* p) {
    uint32_t a;
    asm("{ .reg .u64 t; cvta.to.shared.u64 t, %1; cvt.u32.u64 %0, t; }" : "=r"(a) : "l"(p));
    return a;
}
__device__ __forceinline__ void ldm_x4(uint32_t* r, uint32_t addr) {
    asm volatile("ldmatrix.sync.aligned.m8n8.x4.shared.b16 {%0,%1,%2,%3}, [%4];"
                 : "=r"(r[0]), "=r"(r[1]), "=r"(r[2]), "=r"(r[3]) : "r"(addr));
}
__device__ __forceinline__ void mma_f16(float* c, const uint32_t* a, const uint32_t* b) {
    asm("mma.sync.aligned.m16n8k16.row.col.f32.f16.f16.f32 "
        "{%0,%1,%2,%3},{%4,%5,%6,%7},{%8,%9},{%0,%1,%2,%3};"
        : "+f"(c[0]), "+f"(c[1]), "+f"(c[2]), "+f"(c[3])
        : "r"(a[0]), "r"(a[1]), "r"(a[2]), "r"(a[3]), "r"(b[0]), "r"(b[1]));
}
__device__ __forceinline__ void cp16(uint32_t dst, const void* src) {
    asm volatile("cp.async.cg.shared.global [%0], [%1], 16;"
                 :: "r"(dst), "l"(__cvta_generic_to_global(src)) : "memory");
}
#define CP_COMMIT() asm volatile("cp.async.commit_group;" ::: "memory")
#define CP_WAIT(n)  asm volatile("cp.async.wait_group %0;" :: "n"(n) : "memory")

// ---------------- pk12: folded front-end (blocks 0-11) + tiled weight transposes ----------------
// transpose tiles: Wmsg 128, Whyp 128, Wout 192, Wlin 16, Wqz 8 => 472 tiles
#define PK12_TBLK 472
__global__ void __launch_bounds__(256)
pk12(const float* __restrict__ W_in, const float* __restrict__ b_in,
     const float* __restrict__ W_pos, const float* __restrict__ b_pos,
     const float* __restrict__ W_fc2,
     const float* __restrict__ W_msg, const float* __restrict__ W_hyp,
     const float* __restrict__ W_out, const float* __restrict__ W_line,
     const float* __restrict__ W_qz) {
    if (blockIdx.x >= 12) {
        // 32x32 tile transpose: W[K x N] row-major -> Wt[N x K] fp16
        __shared__ float ts[32][33];
        int t = blockIdx.x - 12;
        const float* W; __half* Wt; int K, N, tk, tn;
        if (t < 128)      { W = W_msg;  Wt = g_Wmsg_t; K = 512;  N = 256; t -= 0;   tk = t >> 3; tn = t & 7; }
        else if (t < 256) { W = W_hyp;  Wt = g_Whyp_t; K = 512;  N = 256; t -= 128; tk = t >> 3; tn = t & 7; }
        else if (t < 448) { W = W_out;  Wt = g_Wout_t; K = 1536; N = 128; t -= 256; tk = t >> 2; tn = t & 3; }
        else if (t < 464) { W = W_line; Wt = g_Wlin_t; K = 256;  N = 64;  t -= 448; tk = t >> 1; tn = t & 1; }
        else              { W = W_qz;   Wt = g_Wqz_t;  K = 128;  N = 64;  t -= 464; tk = t >> 1; tn = t & 1; }
        const int tx = threadIdx.x & 31, ty = threadIdx.x >> 5;  // 32 x 8
        #pragma unroll
        for (int i = 0; i < 4; i++) {
            int r = ty + 8 * i;
            ts[r][tx] = W[(size_t)(tk * 32 + r) * N + tn * 32 + tx];
        }
        __syncthreads();
        #pragma unroll
        for (int i = 0; i < 4; i++) {
            int n = tn * 32 + ty + 8 * i;
            Wt[(size_t)n * K + tk * 32 + tx] = __float2half(ts[tx][ty + 8 * i]);
        }
        return;
    }
    __shared__ float pe[256];
    __shared__ float sM4[4 * 256];
    __shared__ float sbt[256];
    const int t = blockIdx.x, d = threadIdx.x;
    {
        int k = d, i2 = k & ~1;
        float div = expf(-logf(10000.0f) * (float)i2 / 256.0f);
        float arg = (float)t * div;
        pe[k] = (k & 1) ? cosf(arg) : sinf(arg);
    }
    __syncthreads();
    float m[4] = {0.f, 0.f, 0.f, 0.f};
    float bb = 0.f;
    for (int k = 0; k < 256; k++) {
        float w = W_pos[k * 256 + d];
        #pragma unroll
        for (int r = 0; r < 4; r++) m[r] += W_in[r * 256 + k] * w;
        bb += b_in[k] * w;
    }
    float acc = bb + b_pos[d];
    for (int k = 0; k < 256; k++)
        acc += pe[k] * W_pos[(256 + k) * 256 + d];
    #pragma unroll
    for (int r = 0; r < 4; r++) sM4[r * 256 + d] = m[r];
    sbt[d] = acc;
    __syncthreads();
    float accW[4] = {0.f, 0.f, 0.f, 0.f};
    float accC = 0.f;
    #pragma unroll 4
    for (int mm = 0; mm < 256; mm++) {
        float w = W_fc2[(size_t)((t << 8) + mm) * 256 + d];
        #pragma unroll
        for (int r = 0; r < 4; r++) accW[r] += sM4[r * 256 + mm] * w;
        accC += sbt[mm] * w;
    }
    #pragma unroll
    for (int r = 0; r < 4; r++) g_Weff[(t * 4 + r) * 256 + d] = accW[r];
    g_ceffp[t * 256 + d] = accC;
}

// ---------------- pk3: fold fc3 (49 blocks) ----------------
__global__ void __launch_bounds__(256)
pk3(const float* __restrict__ W_fc3, const float* __restrict__ b_fc3,
    const float* __restrict__ b_fc2) {
    const int d = threadIdx.x;
    if (blockIdx.x < 48) {
        const int i = blockIdx.x;
        float a0 = 0.f, a1 = 0.f, a2 = 0.f, a3 = 0.f;
        #pragma unroll 4
        for (int m = 0; m < 256; m += 4) {
            a0 += g_Weff[i * 256 + m + 0] * W_fc3[(m + 0) * 256 + d];
            a1 += g_Weff[i * 256 + m + 1] * W_fc3[(m + 1) * 256 + d];
            a2 += g_Weff[i * 256 + m + 2] * W_fc3[(m + 2) * 256 + d];
            a3 += g_Weff[i * 256 + m + 3] * W_fc3[(m + 3) * 256 + d];
        }
        g_G[i * 256 + d] = (a0 + a1) + (a2 + a3);
    } else {
        __shared__ float ce[256];
        float s = b_fc2[d];
        #pragma unroll
        for (int t = 0; t < 12; t++) s += g_ceffp[t * 256 + d];
        ce[d] = s;
        __syncthreads();
        float a0 = b_fc3[d], a1 = 0.f, a2 = 0.f, a3 = 0.f;
        #pragma unroll 4
        for (int m = 0; m < 256; m += 4) {
            a0 += ce[m + 0] * W_fc3[(m + 0) * 256 + d];
            a1 += ce[m + 1] * W_fc3[(m + 1) * 256 + d];
            a2 += ce[m + 2] * W_fc3[(m + 2) * 256 + d];
            a3 += ce[m + 3] * W_fc3[(m + 3) * 256 + d];
        }
        float acc = (a0 + a1) + (a2 + a3);
        #pragma unroll
        for (int n = 0; n < 11; n++) g_cb[n * 256 + d] = acc + W_fc3[(256 + n) * 256 + d];
    }
}

// ---------------- per-scene kernel ----------------
__global__ void __launch_bounds__(256)
scene_kernel(const float* __restrict__ inputs) {
    __shared__ float inT[48 * 12];
    __shared__ float ft[11 * 256];
    __shared__ float dot_s[121];
    __shared__ float corr_s[121];
    __shared__ float2 attn2_s[121];
    __shared__ float nrm[11];
    __shared__ float wmin_s[8];
    __shared__ float thr_s;

    const int b = blockIdx.x, tid = threadIdx.x;
    const float* ip = inputs + (size_t)b * 11 * 48;
    if (tid < 48) inT[tid * 12 + 11] = 0.f;
    for (int i = tid; i < 528; i += 256) {
        int n = i / 48, k = i - n * 48;
        inT[k * 12 + n] = ip[i];
    }
    __syncthreads();

    float acc[11];
    #pragma unroll
    for (int n = 0; n < 11; n++) acc[n] = g_cb[n * 256 + tid];
    for (int k = 0; k < 48; k++) {
        float g = g_G[k * 256 + tid];
        float4 v0 = *(const float4*)&inT[k * 12 + 0];
        float4 v1 = *(const float4*)&inT[k * 12 + 4];
        float4 v2 = *(const float4*)&inT[k * 12 + 8];
        acc[0] += v0.x * g; acc[1] += v0.y * g; acc[2] += v0.z * g; acc[3] += v0.w * g;
        acc[4] += v1.x * g; acc[5] += v1.y * g; acc[6] += v1.z * g; acc[7] += v1.w * g;
        acc[8] += v2.x * g; acc[9] += v2.y * g; acc[10] += v2.z * g;
    }
    const size_t rowbase = (size_t)b * 11;
    #pragma unroll
    for (int n = 0; n < 11; n++) {
        ft[n * 256 + tid] = acc[n];
        g_ft[(rowbase + n) * 256 + tid] = __float2half(acc[n]);
    }
    __syncthreads();

    const int warp = tid >> 5, lane = tid & 31;
    for (int p = warp; p < 121; p += 8) {
        int n = p / 11, m = p % 11;
        if (m < n) continue;
        float s = 0.f;
        #pragma unroll
        for (int i = 0; i < 8; i++)
            s += ft[n * 256 + lane + 32 * i] * ft[m * 256 + lane + 32 * i];
        #pragma unroll
        for (int o = 16; o > 0; o >>= 1) s += __shfl_down_sync(0xffffffffu, s, o);
        if (lane == 0) { dot_s[n * 11 + m] = s; dot_s[m * 11 + n] = s; }
    }
    __syncthreads();
    if (tid < 11) nrm[tid] = sqrtf(dot_s[tid * 11 + tid]);
    __syncthreads();
    if (tid < 121) {
        int n = tid / 11, m = tid % 11;
        corr_s[tid] = dot_s[tid] / (nrm[n] * nrm[m]);
    }
    __syncthreads();
    {
        float v = (tid < 121) ? corr_s[tid] : 1e30f;
        #pragma unroll
        for (int o = 16; o > 0; o >>= 1) v = fminf(v, __shfl_down_sync(0xffffffffu, v, o));
        if (lane == 0) wmin_s[warp] = v;
    }
    __syncthreads();
    if (tid == 0) {
        float a = fminf(fminf(wmin_s[0], wmin_s[1]), fminf(wmin_s[2], wmin_s[3]));
        float thr;
        if (a < 0.4f)                  thr = 0.4f;
        else if (a > 0.4f && a < 0.6f) thr = a + 0.1f;
        else                           thr = a + 0.03f;
        thr_s = thr;
    }
    __syncthreads();
    if (tid < 11) {
        const int n = tid;
        const float thr = thr_s;
        float rs = 0.f;
        #pragma unroll
        for (int m = 0; m < 11; m++) rs += (corr_s[n * 11 + m] >= thr) ? 1.0f : 0.0f;
        const float inv = 1.0f / fmaxf(rs, 1.0f);
        const float sc = 0.0625f;
        float mx = -1e30f;
        #pragma unroll
        for (int m = 0; m < 11; m++) mx = fmaxf(mx, dot_s[n * 11 + m] * sc);
        float e[11], se = 0.f;
        #pragma unroll
        for (int m = 0; m < 11; m++) { e[m] = expf(dot_s[n * 11 + m] * sc - mx); se += e[m]; }
        const float is = 1.0f / se;
        #pragma unroll
        for (int m = 0; m < 11; m++) {
            float ar = (corr_s[n * 11 + m] >= thr) ? inv : 0.0f;
            attn2_s[n * 11 + m] = make_float2(e[m] * is, ar);
        }
    }
    __syncthreads();
    // n-outer mixing: scalar accumulators, same m-order => bit-identical
    #pragma unroll
    for (int n = 0; n < 11; n++) {
        float sa = 0.f, sh = 0.f;
        #pragma unroll
        for (int m = 0; m < 11; m++) {
            float2 w = attn2_s[n * 11 + m];
            sa += w.x * acc[m];
            sh += w.y * acc[m];
        }
        g_agg[(rowbase + n) * 256 + tid] = __float2half(sa);
        g_hag[(rowbase + n) * 256 + tid] = __float2half(sh);
    }
}

// ---------------- fused msg+hyp GEMM (z selects problem) ----------------
__global__ void __launch_bounds__(256)
k_mma2(const float* __restrict__ b_msg, const float* __restrict__ b_hyp) {
    constexpr int NTILE = 128;
    constexpr int NF = NTILE / 16;
    constexpr int STAGE = 16384 + NTILE * 128;
    extern __shared__ char smx[];
    const uint32_t sb = smem_u32(smx);
    const int tid = threadIdx.x, lane = tid & 31, wid = tid >> 5;
    const int wm = wid >> 1, wn = wid & 1;
    const int m0 = blockIdx.y * 128, n0 = blockIdx.x * NTILE;
    const int z = blockIdx.z;
    const __half* A1 = g_ft;
    const __half* A2 = z ? g_hag : g_agg;
    const __half* Bt = z ? g_Whyp_t : g_Wmsg_t;
    const float* bias = z ? b_hyp : b_msg;
    __half* out = z ? g_hyp : g_int;
    const int NIT = 8;   // K = 512
    const int t4 = lane >> 3;
    const int aRow = (lane & 7) + (t4 & 1) * 8;
    const int aK8  = (t4 >> 1) * 8;
    const int bNl  = (t4 >> 1) * 8 + (lane & 7);
    const int bK8  = (t4 & 1) * 8;

    auto issue = [&](int it) {
        const int kk = it * 64;
        const uint32_t sA = sb + (it & 1) * STAGE;
        #pragma unroll
        for (int v = 0; v < 4; v++) {
            int idx = tid + v * 256;
            int rr = idx >> 3, g = idx & 7;
            const __half* s = (kk < 256)
                ? A1 + (size_t)(m0 + rr) * 256 + kk + g * 8
                : A2 + (size_t)(m0 + rr) * 256 + (kk - 256) + g * 8;
            cp16(sA + SWZ((uint32_t)(rr * 128 + g * 16)), s);
        }
        #pragma unroll
        for (int v = 0; v < NTILE / 32; v++) {
            int idx = tid + v * 256;
            int rr = idx >> 3, g = idx & 7;
            cp16(sA + 16384 + SWZ((uint32_t)(rr * 128 + g * 16)),
                 Bt + (size_t)(n0 + rr) * 512 + kk + g * 8);
        }
        CP_COMMIT();
    };

    float c[2][NF][4];
    #pragma unroll
    for (int mi = 0; mi < 2; mi++)
        #pragma unroll
        for (int f = 0; f < NF; f++)
            #pragma unroll
            for (int q = 0; q < 4; q++) c[mi][f][q] = 0.f;

    issue(0);
    for (int it = 0; it < NIT; it++) {
        if (it + 1 < NIT) { issue(it + 1); CP_WAIT(1); } else { CP_WAIT(0); }
        __syncthreads();
        const uint32_t sA = sb + (it & 1) * STAGE;
        const uint32_t sB = sA + 16384;
        #pragma unroll
        for (int k16 = 0; k16 < 4; k16++) {
            uint32_t a[2][4], bf[NF][2];
            #pragma unroll
            for (int mi = 0; mi < 2; mi++) {
                uint32_t off = (uint32_t)((wm * 32 + mi * 16 + aRow) * 128 + k16 * 32 + aK8 * 2);
                ldm_x4(a[mi], sA + SWZ(off));
            }
            #pragma unroll
            for (int fp = 0; fp < NF / 2; fp++) {
                uint32_t off = (uint32_t)((wn * (NTILE / 2) + fp * 16 + bNl) * 128 + k16 * 32 + bK8 * 2);
                uint32_t r4[4];
                ldm_x4(r4, sB + SWZ(off));
                bf[2 * fp][0] = r4[0]; bf[2 * fp][1] = r4[1];
                bf[2 * fp + 1][0] = r4[2]; bf[2 * fp + 1][1] = r4[3];
            }
            #pragma unroll
            for (int mi = 0; mi < 2; mi++)
                #pragma unroll
                for (int f = 0; f < NF; f++) mma_f16(c[mi][f], a[mi], bf[f]);
        }
        __syncthreads();
    }

    const int gID = lane >> 2, tig = lane & 3;
    #pragma unroll
    for (int mi = 0; mi < 2; mi++) {
        const int r0 = m0 + wm * 32 + mi * 16 + gID;
        #pragma unroll
        for (int f = 0; f < NF; f++) {
            const int col = n0 + wn * (NTILE / 2) + f * 8 + tig * 2;
            const float b0 = bias[col], b1 = bias[col + 1];
            float v00 = fmaxf(c[mi][f][0] + b0, 0.f), v01 = fmaxf(c[mi][f][1] + b1, 0.f);
            float v10 = fmaxf(c[mi][f][2] + b0, 0.f), v11 = fmaxf(c[mi][f][3] + b1, 0.f);
            *(__half2*)(out + (size_t)r0 * 256 + col) = __float22half2_rn(make_float2(v00, v01));
            *(__half2*)(out + (size_t)(r0 + 8) * 256 + col) = __float22half2_rn(make_float2(v10, v11));
        }
    }
}

// ---------------- feat GEMM (NTILE=64) ----------------
template<int NTILE>
__global__ void __launch_bounds__(256)
k_mma(const __half* __restrict__ A1, const __half* __restrict__ A2,
      const __half* __restrict__ Bt, const float* __restrict__ bias,
      __half* __restrict__ out, int K, int K1, int N, int relu) {
    constexpr int NF = NTILE / 16;
    constexpr int STAGE = 16384 + NTILE * 128;
    extern __shared__ char smx[];
    const uint32_t sb = smem_u32(smx);
    const int tid = threadIdx.x, lane = tid & 31, wid = tid >> 5;
    const int wm = wid >> 1, wn = wid & 1;
    const int m0 = blockIdx.y * 128, n0 = blockIdx.x * NTILE;
    const int NIT = K / 64;
    const int K2 = K - K1;
    const int t4 = lane >> 3;
    const int aRow = (lane & 7) + (t4 & 1) * 8;
    const int aK8  = (t4 >> 1) * 8;
    const int bNl  = (t4 >> 1) * 8 + (lane & 7);
    const int bK8  = (t4 & 1) * 8;

    auto issue = [&](int it) {
        const int kk = it * 64;
        const uint32_t sA = sb + (it & 1) * STAGE;
        #pragma unroll
        for (int v = 0; v < 4; v++) {
            int idx = tid + v * 256;
            int rr = idx >> 3, g = idx & 7;
            const __half* s = (kk < K1)
                ? A1 + (size_t)(m0 + rr) * K1 + kk + g * 8
                : A2 + (size_t)(m0 + rr) * K2 + (kk - K1) + g * 8;
            cp16(sA + SWZ((uint32_t)(rr * 128 + g * 16)), s);
        }
        #pragma unroll
        for (int v = 0; v < NTILE / 32; v++) {
            int idx = tid + v * 256;
            int rr = idx >> 3, g = idx & 7;
            cp16(sA + 16384 + SWZ((uint32_t)(rr * 128 + g * 16)),
                 Bt + (size_t)(n0 + rr) * K + kk + g * 8);
        }
        CP_COMMIT();
    };

    float c[2][NF][4];
    #pragma unroll
    for (int mi = 0; mi < 2; mi++)
        #pragma unroll
        for (int f = 0; f < NF; f++)
            #pragma unroll
            for (int q = 0; q < 4; q++) c[mi][f][q] = 0.f;

    issue(0);
    for (int it = 0; it < NIT; it++) {
        if (it + 1 < NIT) { issue(it + 1); CP_WAIT(1); } else { CP_WAIT(0); }
        __syncthreads();
        const uint32_t sA = sb + (it & 1) * STAGE;
        const uint32_t sB = sA + 16384;
        #pragma unroll
        for (int k16 = 0; k16 < 4; k16++) {
            uint32_t a[2][4], bf[NF][2];
            #pragma unroll
            for (int mi = 0; mi < 2; mi++) {
                uint32_t off = (uint32_t)((wm * 32 + mi * 16 + aRow) * 128 + k16 * 32 + aK8 * 2);
                ldm_x4(a[mi], sA + SWZ(off));
            }
            #pragma unroll
            for (int fp = 0; fp < NF / 2; fp++) {
                uint32_t off = (uint32_t)((wn * (NTILE / 2) + fp * 16 + bNl) * 128 + k16 * 32 + bK8 * 2);
                uint32_t r4[4];
                ldm_x4(r4, sB + SWZ(off));
                bf[2 * fp][0] = r4[0]; bf[2 * fp][1] = r4[1];
                bf[2 * fp + 1][0] = r4[2]; bf[2 * fp + 1][1] = r4[3];
            }
            #pragma unroll
            for (int mi = 0; mi < 2; mi++)
                #pragma unroll
                for (int f = 0; f < NF; f++) mma_f16(c[mi][f], a[mi], bf[f]);
        }
        __syncthreads();
    }

    const int gID = lane >> 2, tig = lane & 3;
    #pragma unroll
    for (int mi = 0; mi < 2; mi++) {
        const int r0 = m0 + wm * 32 + mi * 16 + gID;
        #pragma unroll
        for (int f = 0; f < NF; f++) {
            const int col = n0 + wn * (NTILE / 2) + f * 8 + tig * 2;
            const float b0 = bias[col], b1 = bias[col + 1];
            float v00 = c[mi][f][0] + b0, v01 = c[mi][f][1] + b1;
            float v10 = c[mi][f][2] + b0, v11 = c[mi][f][3] + b1;
            if (relu) {
                v00 = fmaxf(v00, 0.f); v01 = fmaxf(v01, 0.f);
                v10 = fmaxf(v10, 0.f); v11 = fmaxf(v11, 0.f);
            }
            *(__half2*)(out + (size_t)r0 * N + col) = __float22half2_rn(make_float2(v00, v01));
            *(__half2*)(out + (size_t)(r0 + 8) * N + col) = __float22half2_rn(make_float2(v10, v11));
        }
    }
}

// ---------------- final GEMM: direct fp32 past staging, fused qz epilogue ----------------
#define FSTAGE 32768
#define FQZ_OFF (3 * FSTAGE)              // 98304: W_qz tiles (16KB)
#define A32_OFF (FQZ_OFF + 16384)         // 114688: fp32 past staging, 3 x 34816 (272B/row)
#define A32_STRIDE 34816
#define FTOTAL (A32_OFF + 3 * A32_STRIDE) // 219136
__global__ void __launch_bounds__(256)
k_final(const float* __restrict__ past,
        const float* __restrict__ b_out, const float* __restrict__ b_qz,
        float* __restrict__ out) {
    constexpr int NF = 8;
    extern __shared__ char smx[];
    const uint32_t sb = smem_u32(smx);
    const int tid = threadIdx.x, lane = tid & 31, wid = tid >> 5;
    const int wm = wid >> 1, wn = wid & 1;
    const int m0 = blockIdx.x * 128;
    const int NIT = 24;  // K = 1536; iters 0..14 are fp32 past
    const int t4 = lane >> 3;
    const int aRow = (lane & 7) + (t4 & 1) * 8;
    const int aK8  = (t4 >> 1) * 8;
    const int bNl  = (t4 >> 1) * 8 + (lane & 7);
    const int bK8  = (t4 & 1) * 8;

    auto issue = [&](int it) {
        const int kk = it * 64;
        const uint32_t sA = sb + (it % 3) * FSTAGE;
        if (kk < 960) {
            const uint32_t a32 = sb + A32_OFF + (it % 3) * A32_STRIDE;
            #pragma unroll
            for (int v = 0; v < 8; v++) {
                int idx = tid + v * 256;
                int rr = idx >> 4, g = idx & 15;
                cp16(a32 + rr * 272 + g * 16,
                     past + (size_t)(m0 + rr) * 960 + kk + g * 4);
            }
        } else {
            const __half* src;
            int stride, off;
            if (kk < 1216)      { src = g_ft;  stride = 256; off = kk - 960; }
            else if (kk < 1472) { src = g_int; stride = 256; off = kk - 1216; }
            else                { src = g_fea; stride = 64;  off = kk - 1472; }
            #pragma unroll
            for (int v = 0; v < 4; v++) {
                int idx = tid + v * 256;
                int rr = idx >> 3, g = idx & 7;
                cp16(sA + SWZ((uint32_t)(rr * 128 + g * 16)),
                     src + (size_t)(m0 + rr) * stride + off + g * 8);
            }
        }
        #pragma unroll
        for (int v = 0; v < 4; v++) {
            int idx = tid + v * 256;
            int rr = idx >> 3, g = idx & 7;
            cp16(sA + 16384 + SWZ((uint32_t)(rr * 128 + g * 16)),
                 g_Wout_t + (size_t)rr * 1536 + kk + g * 8);
        }
        CP_COMMIT();
    };

    // prestage W_qz (2 chunks of 64 cols)
    #pragma unroll
    for (int v = 0; v < 4; v++) {
        int idx = tid + v * 256;
        int ch = idx >> 9, ii = idx & 511;
        int rr = ii >> 3, g = ii & 7;
        cp16(sb + FQZ_OFF + ch * 8192 + SWZ((uint32_t)(rr * 128 + g * 16)),
             g_Wqz_t + rr * 128 + ch * 64 + g * 8);
    }
    CP_COMMIT();

    float c[2][NF][4];
    #pragma unroll
    for (int mi = 0; mi < 2; mi++)
        #pragma unroll
        for (int f = 0; f < NF; f++)
            #pragma unroll
            for (int q = 0; q < 4; q++) c[mi][f][q] = 0.f;

    issue(0);
    issue(1);
    for (int it = 0; it < NIT; it++) {
        if (it + 2 < NIT)      { issue(it + 2); CP_WAIT(2); }
        else if (it + 1 < NIT) { CP_WAIT(1); }
        else                   { CP_WAIT(0); }
        __syncthreads();
        const uint32_t sA = sb + (it % 3) * FSTAGE;
        if (it * 64 < 960) {
            const float* a32f = (const float*)(smx + A32_OFF + (it % 3) * A32_STRIDE);
            const int orr = tid >> 1, ohalf = tid & 1;
            #pragma unroll
            for (int j = 0; j < 4; j++) {
                const float* p = a32f + orr * 68 + ohalf * 32 + j * 8;
                float4 u0 = *(const float4*)p;
                float4 u1 = *(const float4*)(p + 4);
                __half2 h0 = __float22half2_rn(make_float2(u0.x, u0.y));
                __half2 h1 = __float22half2_rn(make_float2(u0.z, u0.w));
                __half2 h2 = __float22half2_rn(make_float2(u1.x, u1.y));
                __half2 h3 = __float22half2_rn(make_float2(u1.z, u1.w));
                uint4 pk;
                pk.x = *(uint32_t*)&h0; pk.y = *(uint32_t*)&h1;
                pk.z = *(uint32_t*)&h2; pk.w = *(uint32_t*)&h3;
                *(uint4*)(smx + (it % 3) * FSTAGE +
                          SWZ((uint32_t)(orr * 128 + ohalf * 64 + j * 16))) = pk;
            }
            __syncthreads();
        }
        const uint32_t sB = sA + 16384;
        #pragma unroll
        for (int k16 = 0; k16 < 4; k16++) {
            uint32_t a[2][4], bf[NF][2];
            #pragma unroll
            for (int mi = 0; mi < 2; mi++) {
                uint32_t off = (uint32_t)((wm * 32 + mi * 16 + aRow) * 128 + k16 * 32 + aK8 * 2);
                ldm_x4(a[mi], sA + SWZ(off));
            }
            #pragma unroll
            for (int fp = 0; fp < 4; fp++) {
                uint32_t off = (uint32_t)((wn * 64 + fp * 16 + bNl) * 128 + k16 * 32 + bK8 * 2);
                uint32_t r4[4];
                ldm_x4(r4, sB + SWZ(off));
                bf[2 * fp][0] = r4[0]; bf[2 * fp][1] = r4[1];
                bf[2 * fp + 1][0] = r4[2]; bf[2 * fp + 1][1] = r4[3];
            }
            #pragma unroll
            for (int mi = 0; mi < 2; mi++)
                #pragma unroll
                for (int f = 0; f < NF; f++) mma_f16(c[mi][f], a[mi], bf[f]);
        }
        __syncthreads();
    }

    // epilogue 1: h = relu(c + b_out) -> fp16 tiles in smem
    const int gID = lane >> 2, tig = lane & 3;
    #pragma unroll
    for (int mi = 0; mi < 2; mi++) {
        const int r0 = wm * 32 + mi * 16 + gID;
        #pragma unroll
        for (int f = 0; f < NF; f++) {
            const int col = wn * 64 + f * 8 + tig * 2;
            const float b0 = b_out[col], b1 = b_out[col + 1];
            float v00 = fmaxf(c[mi][f][0] + b0, 0.f), v01 = fmaxf(c[mi][f][1] + b1, 0.f);
            float v10 = fmaxf(c[mi][f][2] + b0, 0.f), v11 = fmaxf(c[mi][f][3] + b1, 0.f);
            const int ch = col >> 6;
            *(__half2*)(smx + ch * 16384 + SWZ((uint32_t)(r0 * 128 + (col & 63) * 2))) =
                __float22half2_rn(make_float2(v00, v01));
            *(__half2*)(smx + ch * 16384 + SWZ((uint32_t)((r0 + 8) * 128 + (col & 63) * 2))) =
                __float22half2_rn(make_float2(v10, v11));
        }
    }
    __syncthreads();

    // epilogue 2: out = h @ W_qz + b_qz
    float c2[2][4][4];
    #pragma unroll
    for (int mi = 0; mi < 2; mi++)
        #pragma unroll
        for (int f = 0; f < 4; f++)
            #pragma unroll
            for (int q = 0; q < 4; q++) c2[mi][f][q] = 0.f;
    #pragma unroll
    for (int ch = 0; ch < 2; ch++) {
        const uint32_t sAh = sb + ch * 16384;
        const uint32_t sBq = sb + FQZ_OFF + ch * 8192;
        #pragma unroll
        for (int k16 = 0; k16 < 4; k16++) {
            uint32_t a[2][4], bf[4][2];
            #pragma unroll
            for (int mi = 0; mi < 2; mi++) {
                uint32_t off = (uint32_t)((wm * 32 + mi * 16 + aRow) * 128 + k16 * 32 + aK8 * 2);
                ldm_x4(a[mi], sAh + SWZ(off));
            }
            #pragma unroll
            for (int fp = 0; fp < 2; fp++) {
                uint32_t off = (uint32_t)((wn * 32 + fp * 16 + bNl) * 128 + k16 * 32 + bK8 * 2);
                uint32_t r4[4];
                ldm_x4(r4, sBq + SWZ(off));
                bf[2 * fp][0] = r4[0]; bf[2 * fp][1] = r4[1];
                bf[2 * fp + 1][0] = r4[2]; bf[2 * fp + 1][1] = r4[3];
            }
            #pragma unroll
            for (int mi = 0; mi < 2; mi++)
                #pragma unroll
                for (int f = 0; f < 4; f++) mma_f16(c2[mi][f], a[mi], bf[f]);
        }
    }
    #pragma unroll
    for (int mi = 0; mi < 2; mi++) {
        const int r0 = m0 + wm * 32 + mi * 16 + gID;
        #pragma unroll
        for (int f = 0; f < 4; f++) {
            const int col = wn * 32 + f * 8 + tig * 2;
            const float b0 = b_qz[col], b1 = b_qz[col + 1];
            *(float2*)(out + (size_t)r0 * 64 + col) =
                make_float2(c2[mi][f][0] + b0, c2[mi][f][1] + b1);
            *(float2*)(out + (size_t)(r0 + 8) * 64 + col) =
                make_float2(c2[mi][f][2] + b0, c2[mi][f][3] + b1);
        }
    }
}

// ---------------- launch ----------------
extern "C" void kernel_launch(void* const* d_in, const int* in_sizes, int n_in,
                              void* d_out, int out_size) {
    const float* inputs = (const float*)d_in[0];
    const float* past   = (const float*)d_in[1];
    const float* W_in   = (const float*)d_in[2];
    const float* b_in   = (const float*)d_in[3];
    const float* W_pos  = (const float*)d_in[4];
    const float* b_pos  = (const float*)d_in[5];
    const float* W_fc2  = (const float*)d_in[6];
    const float* b_fc2  = (const float*)d_in[7];
    const float* W_fc3  = (const float*)d_in[8];
    const float* b_fc3  = (const float*)d_in[9];
    const float* W_msg  = (const float*)d_in[10];
    const float* b_msg  = (const float*)d_in[11];
    const float* W_hyp  = (const float*)d_in[12];
    const float* b_hyp  = (const float*)d_in[13];
    const float* W_line = (const float*)d_in[14];
    const float* W_out  = (const float*)d_in[15];
    const float* b_out  = (const float*)d_in[16];
    const float* W_qz   = (const float*)d_in[17];
    const float* b_qz   = (const float*)d_in[18];
    float* out = (float*)d_out;

    void *pHyp, *pFea, *pZero, *pWlin;
    cudaGetSymbolAddress(&pHyp,  g_hyp);
    cudaGetSymbolAddress(&pFea,  g_fea);
    cudaGetSymbolAddress(&pZero, g_zero64);
    cudaGetSymbolAddress(&pWlin, g_Wlin_t);

    cudaFuncSetAttribute(k_mma2,    cudaFuncAttributeMaxDynamicSharedMemorySize, 2 * 32768);
    cudaFuncSetAttribute(k_mma<64>, cudaFuncAttributeMaxDynamicSharedMemorySize, 2 * 24576);
    cudaFuncSetAttribute(k_final,   cudaFuncAttributeMaxDynamicSharedMemorySize, FTOTAL);

    pk12<<<12 + PK12_TBLK, 256>>>(W_in, b_in, W_pos, b_pos, W_fc2,
                                  W_msg, W_hyp, W_out, W_line, W_qz);
    pk3<<<49, 256>>>(W_fc3, b_fc3, b_fc2);
    scene_kernel<<<B_SZ, 256>>>(inputs);

    // fused: inter = relu([ft|agg]@Wmsg+b) ; hyp = relu([ft|hag]@Whyp+b)
    k_mma2<<<dim3(2, MTILES, 2), 256, 2 * 32768>>>(b_msg, b_hyp);
    // feat = hyp @ W_line
    k_mma<64><<<dim3(1, MTILES), 256, 2 * 24576>>>(
        (const __half*)pHyp, (const __half*)pHyp, (const __half*)pWlin, (const float*)pZero,
        (__half*)pFea, 256, 256, 64, 0);
    // h = relu([past|ft|inter|feat] @ W_out + b_out); out = h @ W_qz + b_qz
    k_final<<<MTILES, 256, FTOTAL>>>(past, b_out, b_qz, out);
}

// round 17
// speedup vs baseline: 1.0095x; 1.0095x over previous
#include <cuda_runtime.h>
#include <cuda_fp16.h>
#include <math.h>
#include <stdint.h>

// Problem constants
#define B_SZ   4096
#define N_AG   11
#define BN_ROWS (B_SZ * N_AG)      // 45056
#define MTILES  (BN_ROWS / 128)    // 352
#define KF      1728               // final GEMM K: 960 past + 256 ft + 256 int + 256 hyp

// ---------------- device scratch ----------------
__device__ float g_Weff[48 * 256];
__device__ float g_ceffp[12 * 256];
__device__ float g_G[48 * 256];
__device__ float g_cb[11 * 256];

// fp16 activations
__device__ __half g_ft [(size_t)BN_ROWS * 256];
__device__ __half g_agg[(size_t)BN_ROWS * 256];
__device__ __half g_hag[(size_t)BN_ROWS * 256];
__device__ __half g_int[(size_t)BN_ROWS * 256];
__device__ __half g_hyp[(size_t)BN_ROWS * 256];
// fp16 transposed weights [n][K]
__device__ __half g_Wmsg_t[256 * 512];
__device__ __half g_Whyp_t[256 * 512];
__device__ __half g_Wcmb_t[128 * KF];   // [Wout_t[:,0:1472] | (W_line@W_out[1472:])^T]
__device__ __half g_Wqz_t [64 * 128];

// ---------------- helpers ----------------
#define SWZ(o) ((o) ^ (((o) >> 3) & 0x70))
__device__ __forceinline__ uint32_t smem_u32(const void* p) {
    uint32_t a;
    asm("{ .reg .u64 t; cvta.to.shared.u64 t, %1; cvt.u32.u64 %0, t; }" : "=r"(a) : "l"(p));
    return a;
}
__device__ __forceinline__ void ldm_x4(uint32_t* r, uint32_t addr) {
    asm volatile("ldmatrix.sync.aligned.m8n8.x4.shared.b16 {%0,%1,%2,%3}, [%4];"
                 : "=r"(r[0]), "=r"(r[1]), "=r"(r[2]), "=r"(r[3]) : "r"(addr));
}
__device__ __forceinline__ void mma_f16(float* c, const uint32_t* a, const uint32_t* b) {
    asm("mma.sync.aligned.m16n8k16.row.col.f32.f16.f16.f32 "
        "{%0,%1,%2,%3},{%4,%5,%6,%7},{%8,%9},{%0,%1,%2,%3};"
        : "+f"(c[0]), "+f"(c[1]), "+f"(c[2]), "+f"(c[3])
        : "r"(a[0]), "r"(a[1]), "r"(a[2]), "r"(a[3]), "r"(b[0]), "r"(b[1]));
}
__device__ __forceinline__ void cp16(uint32_t dst, const void* src) {
    asm volatile("cp.async.cg.shared.global [%0], [%1], 16;"
                 :: "r"(dst), "l"(__cvta_generic_to_global(src)) : "memory");
}
#define CP_COMMIT() asm volatile("cp.async.commit_group;" ::: "memory")
#define CP_WAIT(n)  asm volatile("cp.async.wait_group %0;" :: "n"(n) : "memory")

// ---------------- pk12: front-end fold (0-11) + transposes (12..459) + Weq (460..587) ----------------
// transpose tiles: Wmsg 128, Whyp 128, Wout 184 (k<1472 only), Wqz 8 => 448
#define PK12_NBLK 588
__global__ void __launch_bounds__(256)
pk12(const float* __restrict__ W_in, const float* __restrict__ b_in,
     const float* __restrict__ W_pos, const float* __restrict__ b_pos,
     const float* __restrict__ W_fc2,
     const float* __restrict__ W_msg, const float* __restrict__ W_hyp,
     const float* __restrict__ W_out, const float* __restrict__ W_line,
     const float* __restrict__ W_qz) {
    if (blockIdx.x >= 460) {
        // Weq[k][n] = sum_f W_line[k*64+f] * W_out[(1472+f)*128 + n]
        // stored transposed: g_Wcmb_t[n*KF + 1472 + k]
        int idx = (blockIdx.x - 460) * 256 + threadIdx.x;   // 0..32767
        int k = idx >> 7, n = idx & 127;
        float acc = 0.f;
        #pragma unroll 8
        for (int f = 0; f < 64; f++)
            acc += W_line[k * 64 + f] * W_out[(size_t)(1472 + f) * 128 + n];
        g_Wcmb_t[(size_t)n * KF + 1472 + k] = __float2half(acc);
        return;
    }
    if (blockIdx.x >= 12) {
        // 32x32 tile transpose: W[K x N] row-major -> Wt[N x KS] fp16
        __shared__ float ts[32][33];
        int t = blockIdx.x - 12;
        const float* W; __half* Wt; int N, KS, tk, tn;
        if (t < 128)      { W = W_msg; Wt = g_Wmsg_t; N = 256; KS = 512;  t -= 0;   tk = t >> 3; tn = t & 7; }
        else if (t < 256) { W = W_hyp; Wt = g_Whyp_t; N = 256; KS = 512;  t -= 128; tk = t >> 3; tn = t & 7; }
        else if (t < 440) { W = W_out; Wt = g_Wcmb_t; N = 128; KS = KF;   t -= 256; tk = t >> 2; tn = t & 3; }
        else              { W = W_qz;  Wt = g_Wqz_t;  N = 64;  KS = 128;  t -= 440; tk = t >> 1; tn = t & 1; }
        const int tx = threadIdx.x & 31, ty = threadIdx.x >> 5;  // 32 x 8
        #pragma unroll
        for (int i = 0; i < 4; i++) {
            int r = ty + 8 * i;
            ts[r][tx] = W[(size_t)(tk * 32 + r) * N + tn * 32 + tx];
        }
        __syncthreads();
        #pragma unroll
        for (int i = 0; i < 4; i++) {
            int n = tn * 32 + ty + 8 * i;
            Wt[(size_t)n * KS + tk * 32 + tx] = __float2half(ts[tx][ty + 8 * i]);
        }
        return;
    }
    __shared__ float pe[256];
    __shared__ float sM4[4 * 256];
    __shared__ float sbt[256];
    const int t = blockIdx.x, d = threadIdx.x;
    {
        int k = d, i2 = k & ~1;
        float div = expf(-logf(10000.0f) * (float)i2 / 256.0f);
        float arg = (float)t * div;
        pe[k] = (k & 1) ? cosf(arg) : sinf(arg);
    }
    __syncthreads();
    float m[4] = {0.f, 0.f, 0.f, 0.f};
    float bb = 0.f;
    for (int k = 0; k < 256; k++) {
        float w = W_pos[k * 256 + d];
        #pragma unroll
        for (int r = 0; r < 4; r++) m[r] += W_in[r * 256 + k] * w;
        bb += b_in[k] * w;
    }
    float acc = bb + b_pos[d];
    for (int k = 0; k < 256; k++)
        acc += pe[k] * W_pos[(256 + k) * 256 + d];
    #pragma unroll
    for (int r = 0; r < 4; r++) sM4[r * 256 + d] = m[r];
    sbt[d] = acc;
    __syncthreads();
    float accW[4] = {0.f, 0.f, 0.f, 0.f};
    float accC = 0.f;
    #pragma unroll 4
    for (int mm = 0; mm < 256; mm++) {
        float w = W_fc2[(size_t)((t << 8) + mm) * 256 + d];
        #pragma unroll
        for (int r = 0; r < 4; r++) accW[r] += sM4[r * 256 + mm] * w;
        accC += sbt[mm] * w;
    }
    #pragma unroll
    for (int r = 0; r < 4; r++) g_Weff[(t * 4 + r) * 256 + d] = accW[r];
    g_ceffp[t * 256 + d] = accC;
}

// ---------------- pk3: fold fc3 (49 blocks) ----------------
__global__ void __launch_bounds__(256)
pk3(const float* __restrict__ W_fc3, const float* __restrict__ b_fc3,
    const float* __restrict__ b_fc2) {
    const int d = threadIdx.x;
    if (blockIdx.x < 48) {
        const int i = blockIdx.x;
        float a0 = 0.f, a1 = 0.f, a2 = 0.f, a3 = 0.f;
        #pragma unroll 4
        for (int m = 0; m < 256; m += 4) {
            a0 += g_Weff[i * 256 + m + 0] * W_fc3[(m + 0) * 256 + d];
            a1 += g_Weff[i * 256 + m + 1] * W_fc3[(m + 1) * 256 + d];
            a2 += g_Weff[i * 256 + m + 2] * W_fc3[(m + 2) * 256 + d];
            a3 += g_Weff[i * 256 + m + 3] * W_fc3[(m + 3) * 256 + d];
        }
        g_G[i * 256 + d] = (a0 + a1) + (a2 + a3);
    } else {
        __shared__ float ce[256];
        float s = b_fc2[d];
        #pragma unroll
        for (int t = 0; t < 12; t++) s += g_ceffp[t * 256 + d];
        ce[d] = s;
        __syncthreads();
        float a0 = b_fc3[d], a1 = 0.f, a2 = 0.f, a3 = 0.f;
        #pragma unroll 4
        for (int m = 0; m < 256; m += 4) {
            a0 += ce[m + 0] * W_fc3[(m + 0) * 256 + d];
            a1 += ce[m + 1] * W_fc3[(m + 1) * 256 + d];
            a2 += ce[m + 2] * W_fc3[(m + 2) * 256 + d];
            a3 += ce[m + 3] * W_fc3[(m + 3) * 256 + d];
        }
        float acc = (a0 + a1) + (a2 + a3);
        #pragma unroll
        for (int n = 0; n < 11; n++) g_cb[n * 256 + d] = acc + W_fc3[(256 + n) * 256 + d];
    }
}

// ---------------- per-scene kernel ----------------
__global__ void __launch_bounds__(256)
scene_kernel(const float* __restrict__ inputs) {
    __shared__ float inT[48 * 12];
    __shared__ float ft[11 * 256];
    __shared__ float dot_s[121];
    __shared__ float corr_s[121];
    __shared__ float2 attn2_s[121];
    __shared__ float nrm[11];
    __shared__ float wmin_s[8];
    __shared__ float thr_s;

    const int b = blockIdx.x, tid = threadIdx.x;
    const float* ip = inputs + (size_t)b * 11 * 48;
    if (tid < 48) inT[tid * 12 + 11] = 0.f;
    for (int i = tid; i < 528; i += 256) {
        int n = i / 48, k = i - n * 48;
        inT[k * 12 + n] = ip[i];
    }
    __syncthreads();

    float acc[11];
    #pragma unroll
    for (int n = 0; n < 11; n++) acc[n] = g_cb[n * 256 + tid];
    for (int k = 0; k < 48; k++) {
        float g = g_G[k * 256 + tid];
        float4 v0 = *(const float4*)&inT[k * 12 + 0];
        float4 v1 = *(const float4*)&inT[k * 12 + 4];
        float4 v2 = *(const float4*)&inT[k * 12 + 8];
        acc[0] += v0.x * g; acc[1] += v0.y * g; acc[2] += v0.z * g; acc[3] += v0.w * g;
        acc[4] += v1.x * g; acc[5] += v1.y * g; acc[6] += v1.z * g; acc[7] += v1.w * g;
        acc[8] += v2.x * g; acc[9] += v2.y * g; acc[10] += v2.z * g;
    }
    const size_t rowbase = (size_t)b * 11;
    #pragma unroll
    for (int n = 0; n < 11; n++) {
        ft[n * 256 + tid] = acc[n];
        g_ft[(rowbase + n) * 256 + tid] = __float2half(acc[n]);
    }
    __syncthreads();

    const int warp = tid >> 5, lane = tid & 31;
    for (int p = warp; p < 121; p += 8) {
        int n = p / 11, m = p % 11;
        if (m < n) continue;
        float s = 0.f;
        #pragma unroll
        for (int i = 0; i < 8; i++)
            s += ft[n * 256 + lane + 32 * i] * ft[m * 256 + lane + 32 * i];
        #pragma unroll
        for (int o = 16; o > 0; o >>= 1) s += __shfl_down_sync(0xffffffffu, s, o);
        if (lane == 0) { dot_s[n * 11 + m] = s; dot_s[m * 11 + n] = s; }
    }
    __syncthreads();
    if (tid < 11) nrm[tid] = sqrtf(dot_s[tid * 11 + tid]);
    __syncthreads();
    if (tid < 121) {
        int n = tid / 11, m = tid % 11;
        corr_s[tid] = dot_s[tid] / (nrm[n] * nrm[m]);
    }
    __syncthreads();
    {
        float v = (tid < 121) ? corr_s[tid] : 1e30f;
        #pragma unroll
        for (int o = 16; o > 0; o >>= 1) v = fminf(v, __shfl_down_sync(0xffffffffu, v, o));
        if (lane == 0) wmin_s[warp] = v;
    }
    __syncthreads();
    if (tid == 0) {
        float a = fminf(fminf(wmin_s[0], wmin_s[1]), fminf(wmin_s[2], wmin_s[3]));
        float thr;
        if (a < 0.4f)                  thr = 0.4f;
        else if (a > 0.4f && a < 0.6f) thr = a + 0.1f;
        else                           thr = a + 0.03f;
        thr_s = thr;
    }
    __syncthreads();
    if (tid < 11) {
        const int n = tid;
        const float thr = thr_s;
        float rs = 0.f;
        #pragma unroll
        for (int m = 0; m < 11; m++) rs += (corr_s[n * 11 + m] >= thr) ? 1.0f : 0.0f;
        const float inv = 1.0f / fmaxf(rs, 1.0f);
        const float sc = 0.0625f;
        float mx = -1e30f;
        #pragma unroll
        for (int m = 0; m < 11; m++) mx = fmaxf(mx, dot_s[n * 11 + m] * sc);
        float e[11], se = 0.f;
        #pragma unroll
        for (int m = 0; m < 11; m++) { e[m] = expf(dot_s[n * 11 + m] * sc - mx); se += e[m]; }
        const float is = 1.0f / se;
        #pragma unroll
        for (int m = 0; m < 11; m++) {
            float ar = (corr_s[n * 11 + m] >= thr) ? inv : 0.0f;
            attn2_s[n * 11 + m] = make_float2(e[m] * is, ar);
        }
    }
    __syncthreads();
    #pragma unroll
    for (int n = 0; n < 11; n++) {
        float sa = 0.f, sh = 0.f;
        #pragma unroll
        for (int m = 0; m < 11; m++) {
            float2 w = attn2_s[n * 11 + m];
            sa += w.x * acc[m];
            sh += w.y * acc[m];
        }
        g_agg[(rowbase + n) * 256 + tid] = __float2half(sa);
        g_hag[(rowbase + n) * 256 + tid] = __float2half(sh);
    }
}

// ---------------- fused msg+hyp GEMM (z selects problem) ----------------
__global__ void __launch_bounds__(256)
k_mma2(const float* __restrict__ b_msg, const float* __restrict__ b_hyp) {
    constexpr int NTILE = 128;
    constexpr int NF = NTILE / 16;
    constexpr int STAGE = 16384 + NTILE * 128;
    extern __shared__ char smx[];
    const uint32_t sb = smem_u32(smx);
    const int tid = threadIdx.x, lane = tid & 31, wid = tid >> 5;
    const int wm = wid >> 1, wn = wid & 1;
    const int m0 = blockIdx.y * 128, n0 = blockIdx.x * NTILE;
    const int z = blockIdx.z;
    const __half* A1 = g_ft;
    const __half* A2 = z ? g_hag : g_agg;
    const __half* Bt = z ? g_Whyp_t : g_Wmsg_t;
    const float* bias = z ? b_hyp : b_msg;
    __half* out = z ? g_hyp : g_int;
    const int NIT = 8;   // K = 512
    const int t4 = lane >> 3;
    const int aRow = (lane & 7) + (t4 & 1) * 8;
    const int aK8  = (t4 >> 1) * 8;
    const int bNl  = (t4 >> 1) * 8 + (lane & 7);
    const int bK8  = (t4 & 1) * 8;

    auto issue = [&](int it) {
        const int kk = it * 64;
        const uint32_t sA = sb + (it & 1) * STAGE;
        #pragma unroll
        for (int v = 0; v < 4; v++) {
            int idx = tid + v * 256;
            int rr = idx >> 3, g = idx & 7;
            const __half* s = (kk < 256)
                ? A1 + (size_t)(m0 + rr) * 256 + kk + g * 8
                : A2 + (size_t)(m0 + rr) * 256 + (kk - 256) + g * 8;
            cp16(sA + SWZ((uint32_t)(rr * 128 + g * 16)), s);
        }
        #pragma unroll
        for (int v = 0; v < NTILE / 32; v++) {
            int idx = tid + v * 256;
            int rr = idx >> 3, g = idx & 7;
            cp16(sA + 16384 + SWZ((uint32_t)(rr * 128 + g * 16)),
                 Bt + (size_t)(n0 + rr) * 512 + kk + g * 8);
        }
        CP_COMMIT();
    };

    float c[2][NF][4];
    #pragma unroll
    for (int mi = 0; mi < 2; mi++)
        #pragma unroll
        for (int f = 0; f < NF; f++)
            #pragma unroll
            for (int q = 0; q < 4; q++) c[mi][f][q] = 0.f;

    issue(0);
    for (int it = 0; it < NIT; it++) {
        if (it + 1 < NIT) { issue(it + 1); CP_WAIT(1); } else { CP_WAIT(0); }
        __syncthreads();
        const uint32_t sA = sb + (it & 1) * STAGE;
        const uint32_t sB = sA + 16384;
        #pragma unroll
        for (int k16 = 0; k16 < 4; k16++) {
            uint32_t a[2][4], bf[NF][2];
            #pragma unroll
            for (int mi = 0; mi < 2; mi++) {
                uint32_t off = (uint32_t)((wm * 32 + mi * 16 + aRow) * 128 + k16 * 32 + aK8 * 2);
                ldm_x4(a[mi], sA + SWZ(off));
            }
            #pragma unroll
            for (int fp = 0; fp < NF / 2; fp++) {
                uint32_t off = (uint32_t)((wn * (NTILE / 2) + fp * 16 + bNl) * 128 + k16 * 32 + bK8 * 2);
                uint32_t r4[4];
                ldm_x4(r4, sB + SWZ(off));
                bf[2 * fp][0] = r4[0]; bf[2 * fp][1] = r4[1];
                bf[2 * fp + 1][0] = r4[2]; bf[2 * fp + 1][1] = r4[3];
            }
            #pragma unroll
            for (int mi = 0; mi < 2; mi++)
                #pragma unroll
                for (int f = 0; f < NF; f++) mma_f16(c[mi][f], a[mi], bf[f]);
        }
        __syncthreads();
    }

    const int gID = lane >> 2, tig = lane & 3;
    #pragma unroll
    for (int mi = 0; mi < 2; mi++) {
        const int r0 = m0 + wm * 32 + mi * 16 + gID;
        #pragma unroll
        for (int f = 0; f < NF; f++) {
            const int col = n0 + wn * (NTILE / 2) + f * 8 + tig * 2;
            const float b0 = bias[col], b1 = bias[col + 1];
            float v00 = fmaxf(c[mi][f][0] + b0, 0.f), v01 = fmaxf(c[mi][f][1] + b1, 0.f);
            float v10 = fmaxf(c[mi][f][2] + b0, 0.f), v11 = fmaxf(c[mi][f][3] + b1, 0.f);
            *(__half2*)(out + (size_t)r0 * 256 + col) = __float22half2_rn(make_float2(v00, v01));
            *(__half2*)(out + (size_t)(r0 + 8) * 256 + col) = __float22half2_rn(make_float2(v10, v11));
        }
    }
}

// ---------------- final GEMM: K=1728 gather (past|ft|int|hyp), fused qz epilogue ----------------
#define FSTAGE 32768
#define FQZ_OFF (3 * FSTAGE)              // 98304: W_qz tiles (16KB)
#define A32_OFF (FQZ_OFF + 16384)         // 114688: fp32 past staging, 3 x 34816 (272B/row)
#define A32_STRIDE 34816
#define FTOTAL (A32_OFF + 3 * A32_STRIDE) // 219136
__global__ void __launch_bounds__(256)
k_final(const float* __restrict__ past,
        const float* __restrict__ b_out, const float* __restrict__ b_qz,
        float* __restrict__ out) {
    constexpr int NF = 8;
    extern __shared__ char smx[];
    const uint32_t sb = smem_u32(smx);
    const int tid = threadIdx.x, lane = tid & 31, wid = tid >> 5;
    const int wm = wid >> 1, wn = wid & 1;
    const int m0 = blockIdx.x * 128;
    const int NIT = 27;  // K = 1728; iters 0..14 are fp32 past
    const int t4 = lane >> 3;
    const int aRow = (lane & 7) + (t4 & 1) * 8;
    const int aK8  = (t4 >> 1) * 8;
    const int bNl  = (t4 >> 1) * 8 + (lane & 7);
    const int bK8  = (t4 & 1) * 8;

    auto issue = [&](int it) {
        const int kk = it * 64;
        const uint32_t sA = sb + (it % 3) * FSTAGE;
        if (kk < 960) {
            const uint32_t a32 = sb + A32_OFF + (it % 3) * A32_STRIDE;
            #pragma unroll
            for (int v = 0; v < 8; v++) {
                int idx = tid + v * 256;
                int rr = idx >> 4, g = idx & 15;
                cp16(a32 + rr * 272 + g * 16,
                     past + (size_t)(m0 + rr) * 960 + kk + g * 4);
            }
        } else {
            const __half* src;
            int off;
            if (kk < 1216)      { src = g_ft;  off = kk - 960; }
            else if (kk < 1472) { src = g_int; off = kk - 1216; }
            else                { src = g_hyp; off = kk - 1472; }
            #pragma unroll
            for (int v = 0; v < 4; v++) {
                int idx = tid + v * 256;
                int rr = idx >> 3, g = idx & 7;
                cp16(sA + SWZ((uint32_t)(rr * 128 + g * 16)),
                     src + (size_t)(m0 + rr) * 256 + off + g * 8);
            }
        }
        #pragma unroll
        for (int v = 0; v < 4; v++) {
            int idx = tid + v * 256;
            int rr = idx >> 3, g = idx & 7;
            cp16(sA + 16384 + SWZ((uint32_t)(rr * 128 + g * 16)),
                 g_Wcmb_t + (size_t)rr * KF + kk + g * 8);
        }
        CP_COMMIT();
    };

    // prestage W_qz (2 chunks of 64 cols)
    #pragma unroll
    for (int v = 0; v < 4; v++) {
        int idx = tid + v * 256;
        int ch = idx >> 9, ii = idx & 511;
        int rr = ii >> 3, g = ii & 7;
        cp16(sb + FQZ_OFF + ch * 8192 + SWZ((uint32_t)(rr * 128 + g * 16)),
             g_Wqz_t + rr * 128 + ch * 64 + g * 8);
    }
    CP_COMMIT();

    float c[2][NF][4];
    #pragma unroll
    for (int mi = 0; mi < 2; mi++)
        #pragma unroll
        for (int f = 0; f < NF; f++)
            #pragma unroll
            for (int q = 0; q < 4; q++) c[mi][f][q] = 0.f;

    issue(0);
    issue(1);
    for (int it = 0; it < NIT; it++) {
        if (it + 2 < NIT)      { issue(it + 2); CP_WAIT(2); }
        else if (it + 1 < NIT) { CP_WAIT(1); }
        else                   { CP_WAIT(0); }
        __syncthreads();
        const uint32_t sA = sb + (it % 3) * FSTAGE;
        if (it * 64 < 960) {
            const float* a32f = (const float*)(smx + A32_OFF + (it % 3) * A32_STRIDE);
            const int orr = tid >> 1, ohalf = tid & 1;
            #pragma unroll
            for (int j = 0; j < 4; j++) {
                const float* p = a32f + orr * 68 + ohalf * 32 + j * 8;
                float4 u0 = *(const float4*)p;
                float4 u1 = *(const float4*)(p + 4);
                __half2 h0 = __float22half2_rn(make_float2(u0.x, u0.y));
                __half2 h1 = __float22half2_rn(make_float2(u0.z, u0.w));
                __half2 h2 = __float22half2_rn(make_float2(u1.x, u1.y));
                __half2 h3 = __float22half2_rn(make_float2(u1.z, u1.w));
                uint4 pk;
                pk.x = *(uint32_t*)&h0; pk.y = *(uint32_t*)&h1;
                pk.z = *(uint32_t*)&h2; pk.w = *(uint32_t*)&h3;
                *(uint4*)(smx + (it % 3) * FSTAGE +
                          SWZ((uint32_t)(orr * 128 + ohalf * 64 + j * 16))) = pk;
            }
            __syncthreads();
        }
        const uint32_t sB = sA + 16384;
        #pragma unroll
        for (int k16 = 0; k16 < 4; k16++) {
            uint32_t a[2][4], bf[NF][2];
            #pragma unroll
            for (int mi = 0; mi < 2; mi++) {
                uint32_t off = (uint32_t)((wm * 32 + mi * 16 + aRow) * 128 + k16 * 32 + aK8 * 2);
                ldm_x4(a[mi], sA + SWZ(off));
            }
            #pragma unroll
            for (int fp = 0; fp < 4; fp++) {
                uint32_t off = (uint32_t)((wn * 64 + fp * 16 + bNl) * 128 + k16 * 32 + bK8 * 2);
                uint32_t r4[4];
                ldm_x4(r4, sB + SWZ(off));
                bf[2 * fp][0] = r4[0]; bf[2 * fp][1] = r4[1];
                bf[2 * fp + 1][0] = r4[2]; bf[2 * fp + 1][1] = r4[3];
            }
            #pragma unroll
            for (int mi = 0; mi < 2; mi++)
                #pragma unroll
                for (int f = 0; f < NF; f++) mma_f16(c[mi][f], a[mi], bf[f]);
        }
        __syncthreads();
    }

    // epilogue 1: h = relu(c + b_out) -> fp16 tiles in smem
    const int gID = lane >> 2, tig = lane & 3;
    #pragma unroll
    for (int mi = 0; mi < 2; mi++) {
        const int r0 = wm * 32 + mi * 16 + gID;
        #pragma unroll
        for (int f = 0; f < NF; f++) {
            const int col = wn * 64 + f * 8 + tig * 2;
            const float b0 = b_out[col], b1 = b_out[col + 1];
            float v00 = fmaxf(c[mi][f][0] + b0, 0.f), v01 = fmaxf(c[mi][f][1] + b1, 0.f);
            float v10 = fmaxf(c[mi][f][2] + b0, 0.f), v11 = fmaxf(c[mi][f][3] + b1, 0.f);
            const int ch = col >> 6;
            *(__half2*)(smx + ch * 16384 + SWZ((uint32_t)(r0 * 128 + (col & 63) * 2))) =
                __float22half2_rn(make_float2(v00, v01));
            *(__half2*)(smx + ch * 16384 + SWZ((uint32_t)((r0 + 8) * 128 + (col & 63) * 2))) =
                __float22half2_rn(make_float2(v10, v11));
        }
    }
    __syncthreads();

    // epilogue 2: out = h @ W_qz + b_qz
    float c2[2][4][4];
    #pragma unroll
    for (int mi = 0; mi < 2; mi++)
        #pragma unroll
        for (int f = 0; f < 4; f++)
            #pragma unroll
            for (int q = 0; q < 4; q++) c2[mi][f][q] = 0.f;
    #pragma unroll
    for (int ch = 0; ch < 2; ch++) {
        const uint32_t sAh = sb + ch * 16384;
        const uint32_t sBq = sb + FQZ_OFF + ch * 8192;
        #pragma unroll
        for (int k16 = 0; k16 < 4; k16++) {
            uint32_t a[2][4], bf[4][2];
            #pragma unroll
            for (int mi = 0; mi < 2; mi++) {
                uint32_t off = (uint32_t)((wm * 32 + mi * 16 + aRow) * 128 + k16 * 32 + aK8 * 2);
                ldm_x4(a[mi], sAh + SWZ(off));
            }
            #pragma unroll
            for (int fp = 0; fp < 2; fp++) {
                uint32_t off = (uint32_t)((wn * 32 + fp * 16 + bNl) * 128 + k16 * 32 + bK8 * 2);
                uint32_t r4[4];
                ldm_x4(r4, sBq + SWZ(off));
                bf[2 * fp][0] = r4[0]; bf[2 * fp][1] = r4[1];
                bf[2 * fp + 1][0] = r4[2]; bf[2 * fp + 1][1] = r4[3];
            }
            #pragma unroll
            for (int mi = 0; mi < 2; mi++)
                #pragma unroll
                for (int f = 0; f < 4; f++) mma_f16(c2[mi][f], a[mi], bf[f]);
        }
    }
    #pragma unroll
    for (int mi = 0; mi < 2; mi++) {
        const int r0 = m0 + wm * 32 + mi * 16 + gID;
        #pragma unroll
        for (int f = 0; f < 4; f++) {
            const int col = wn * 32 + f * 8 + tig * 2;
            const float b0 = b_qz[col], b1 = b_qz[col + 1];
            *(float2*)(out + (size_t)r0 * 64 + col) =
                make_float2(c2[mi][f][0] + b0, c2[mi][f][1] + b1);
            *(float2*)(out + (size_t)(r0 + 8) * 64 + col) =
                make_float2(c2[mi][f][2] + b0, c2[mi][f][3] + b1);
        }
    }
}

// ---------------- launch ----------------
extern "C" void kernel_launch(void* const* d_in, const int* in_sizes, int n_in,
                              void* d_out, int out_size) {
    const float* inputs = (const float*)d_in[0];
    const float* past   = (const float*)d_in[1];
    const float* W_in   = (const float*)d_in[2];
    const float* b_in   = (const float*)d_in[3];
    const float* W_pos  = (const float*)d_in[4];
    const float* b_pos  = (const float*)d_in[5];
    const float* W_fc2  = (const float*)d_in[6];
    const float* b_fc2  = (const float*)d_in[7];
    const float* W_fc3  = (const float*)d_in[8];
    const float* b_fc3  = (const float*)d_in[9];
    const float* W_msg  = (const float*)d_in[10];
    const float* b_msg  = (const float*)d_in[11];
    const float* W_hyp  = (const float*)d_in[12];
    const float* b_hyp  = (const float*)d_in[13];
    const float* W_line = (const float*)d_in[14];
    const float* W_out  = (const float*)d_in[15];
    const float* b_out  = (const float*)d_in[16];
    const float* W_qz   = (const float*)d_in[17];
    const float* b_qz   = (const float*)d_in[18];
    float* out = (float*)d_out;

    cudaFuncSetAttribute(k_mma2,  cudaFuncAttributeMaxDynamicSharedMemorySize, 2 * 32768);
    cudaFuncSetAttribute(k_final, cudaFuncAttributeMaxDynamicSharedMemorySize, FTOTAL);

    pk12<<<PK12_NBLK, 256>>>(W_in, b_in, W_pos, b_pos, W_fc2,
                             W_msg, W_hyp, W_out, W_line, W_qz);
    pk3<<<49, 256>>>(W_fc3, b_fc3, b_fc2);
    scene_kernel<<<B_SZ, 256>>>(inputs);

    // fused: inter = relu([ft|agg]@Wmsg+b) ; hyp = relu([ft|hag]@Whyp+b)
    k_mma2<<<dim3(2, MTILES, 2), 256, 2 * 32768>>>(b_msg, b_hyp);
    // h = relu([past|ft|inter|hyp@fold] @ Wcmb + b_out); out = h @ W_qz + b_qz
    k_final<<<MTILES, 256, FTOTAL>>>(past, b_out, b_qz, out);
}